// round 1
// baseline (speedup 1.0000x reference)
#include <cuda_runtime.h>
#include <math.h>

// Fixed problem envelope (dataset: N=8192, d=1024). Scratch sized for N<=8192.
#define MAXN 8192
#define MAXJT 64   // ceil(8192/128)

#define M_POS 0.5f
#define M_NEG_SIM 0.1f
#define LAM_NEG 1.0f

// Device scratch (allocation-free rule: __device__ globals)
__device__ float g_sq[MAXN];
__device__ float g_invn[MAXN];
__device__ float g_pos_part[MAXJT * MAXN];
__device__ float g_neg_part[MAXJT * MAXN];
__device__ float g_per_row[MAXN];
__device__ int   g_valid[MAXN];

// ---------------------------------------------------------------------------
// Pass 1: per-row squared norm and inverse norm
// ---------------------------------------------------------------------------
__global__ void k_norms(const float* __restrict__ cb, int N, int d) {
    int row = blockIdx.x;
    if (row >= N) return;
    const float* p = cb + (size_t)row * d;
    float s = 0.f;
    if ((d & 3) == 0) {
        const float4* p4 = (const float4*)p;
        int d4 = d >> 2;
        for (int c = threadIdx.x; c < d4; c += blockDim.x) {
            float4 v = p4[c];
            s = fmaf(v.x, v.x, s);
            s = fmaf(v.y, v.y, s);
            s = fmaf(v.z, v.z, s);
            s = fmaf(v.w, v.w, s);
        }
    } else {
        for (int c = threadIdx.x; c < d; c += blockDim.x) s = fmaf(p[c], p[c], s);
    }
    #pragma unroll
    for (int off = 16; off; off >>= 1) s += __shfl_down_sync(0xffffffffu, s, off);
    __shared__ float sh[8];
    if ((threadIdx.x & 31) == 0) sh[threadIdx.x >> 5] = s;
    __syncthreads();
    if (threadIdx.x < 8) {
        float v = sh[threadIdx.x];
        #pragma unroll
        for (int off = 4; off; off >>= 1) v += __shfl_down_sync(0xffu, v, off);
        if (threadIdx.x == 0) {
            g_sq[row]   = v;
            g_invn[row] = rsqrtf(fmaxf(v, 1e-30f));
        }
    }
}

// ---------------------------------------------------------------------------
// Pass 2: fused Gram-tile + loss epilogue.
// 128x128 output tile per block, BK=8, 256 threads, 8x8 micro-tile per thread
// with split-column mapping (cols tx*4 and 64+tx*4) for conflict-free LDS.128.
// Writes per-row (pos,neg) partials per j-tile — deterministic, no atomics.
// ---------------------------------------------------------------------------
__global__ __launch_bounds__(256) void k_main(
    const float* __restrict__ cb,
    const int*   __restrict__ starts,
    const int*   __restrict__ ends,
    const int*   __restrict__ pmaxi,
    int N, int d)
{
    __shared__ __align__(16) float As[8][132];
    __shared__ __align__(16) float Bs[8][132];
    __shared__ float sSqI[128], sInvI[128], sSqJ[128], sInvJ[128];
    __shared__ int   sS[128], sE[128];

    const int tid = threadIdx.x;
    const int tx  = tid & 15;
    const int ty  = tid >> 4;
    const int i0  = blockIdx.y * 128;
    const int j0  = blockIdx.x * 128;

    float acc[8][8];
    #pragma unroll
    for (int a = 0; a < 8; a++)
        #pragma unroll
        for (int b = 0; b < 8; b++) acc[a][b] = 0.f;

    const int lrow = tid >> 1;        // 0..127
    const int lcol = (tid & 1) * 4;   // 0 or 4
    const int gi_ld = i0 + lrow;
    const int gj_ld = j0 + lrow;
    const bool vec_ok = ((d & 3) == 0);

    for (int k0 = 0; k0 < d; k0 += 8) {
        float4 av = make_float4(0.f, 0.f, 0.f, 0.f);
        float4 bv = make_float4(0.f, 0.f, 0.f, 0.f);
        int kb = k0 + lcol;
        if (vec_ok && kb + 3 < d) {
            if (gi_ld < N) av = *(const float4*)(cb + (size_t)gi_ld * d + kb);
            if (gj_ld < N) bv = *(const float4*)(cb + (size_t)gj_ld * d + kb);
        } else {
            float ta[4] = {0.f, 0.f, 0.f, 0.f};
            float tb[4] = {0.f, 0.f, 0.f, 0.f};
            #pragma unroll
            for (int u = 0; u < 4; u++) {
                if (kb + u < d) {
                    if (gi_ld < N) ta[u] = cb[(size_t)gi_ld * d + kb + u];
                    if (gj_ld < N) tb[u] = cb[(size_t)gj_ld * d + kb + u];
                }
            }
            av = make_float4(ta[0], ta[1], ta[2], ta[3]);
            bv = make_float4(tb[0], tb[1], tb[2], tb[3]);
        }
        __syncthreads();
        As[lcol + 0][lrow] = av.x;  As[lcol + 1][lrow] = av.y;
        As[lcol + 2][lrow] = av.z;  As[lcol + 3][lrow] = av.w;
        Bs[lcol + 0][lrow] = bv.x;  Bs[lcol + 1][lrow] = bv.y;
        Bs[lcol + 2][lrow] = bv.z;  Bs[lcol + 3][lrow] = bv.w;
        __syncthreads();

        #pragma unroll
        for (int kk = 0; kk < 8; kk++) {
            float a[8], b[8];
            *(float4*)&a[0] = *(const float4*)&As[kk][ty * 4];
            *(float4*)&a[4] = *(const float4*)&As[kk][64 + ty * 4];
            *(float4*)&b[0] = *(const float4*)&Bs[kk][tx * 4];
            *(float4*)&b[4] = *(const float4*)&Bs[kk][64 + tx * 4];
            #pragma unroll
            for (int ii = 0; ii < 8; ii++)
                #pragma unroll
                for (int jj = 0; jj < 8; jj++)
                    acc[ii][jj] = fmaf(a[ii], b[jj], acc[ii][jj]);
        }
    }

    // Load per-row / per-col metadata for the epilogue
    __syncthreads();
    for (int t = tid; t < 128; t += 256) {
        int gi = i0 + t;
        if (gi < N) {
            sSqI[t] = g_sq[gi];  sInvI[t] = g_invn[gi];
            sS[t] = starts[gi];  sE[t] = ends[gi];
        }
        int gj = j0 + t;
        if (gj < N) {
            sSqJ[t] = g_sq[gj];  sInvJ[t] = g_invn[gj];
        }
    }
    __syncthreads();

    const int M  = min(N, pmaxi[0] + 1);
    const int jt = blockIdx.x;

    #pragma unroll
    for (int ii = 0; ii < 8; ii++) {
        int li = (ii >> 2) * 64 + ty * 4 + (ii & 3);
        int gi = i0 + li;
        float pos = 0.f, neg = 0.f;
        if (gi < M) {
            int   s    = sS[li],   e    = sE[li];
            float sqi  = sSqI[li], invi = sInvI[li];
            #pragma unroll
            for (int jj = 0; jj < 8; jj++) {
                int lj = (jj >> 2) * 64 + tx * 4 + (jj & 3);
                int gj = j0 + lj;
                if (gj < N) {
                    float c = acc[ii][jj];
                    bool pm = (gj >= s) && (gj <= e) && (gj != gi);
                    if (pm) {
                        float d2 = fmaxf(sqi + sSqJ[lj] - 2.f * c, 0.f);
                        float t  = sqrtf(d2) - M_POS;
                        if (t > 0.f) pos = fmaf(t, t, pos);
                    } else {
                        float cs = fminf(1.f, fmaxf(-1.f, c * invi * sInvJ[lj]));
                        float a2 = fabsf(cs) - M_NEG_SIM;
                        if (a2 > 0.f) neg = fmaf(a2, a2, neg);
                    }
                }
            }
        }
        // reduce across the 16 threads (tx) that share this row
        #pragma unroll
        for (int off = 8; off; off >>= 1) {
            pos += __shfl_down_sync(0xffffffffu, pos, off, 16);
            neg += __shfl_down_sync(0xffffffffu, neg, off, 16);
        }
        if (tx == 0 && gi < N) {
            g_pos_part[jt * N + gi] = pos;
            g_neg_part[jt * N + gi] = neg;
        }
    }
}

// ---------------------------------------------------------------------------
// Pass 3: per-row combine with analytic counts
// ---------------------------------------------------------------------------
__global__ void k_rowsum(const int* __restrict__ starts,
                         const int* __restrict__ ends,
                         const int* __restrict__ pmaxi,
                         int N, int njt) {
    int i = blockIdx.x * blockDim.x + threadIdx.x;
    if (i >= N) return;
    int M = min(N, pmaxi[0] + 1);
    float ps = 0.f, ns = 0.f;
    for (int t = 0; t < njt; t++) {
        ps += g_pos_part[t * N + i];
        ns += g_neg_part[t * N + i];
    }
    int s = starts[i], e = ends[i];
    int lo = s < 0 ? 0 : s;
    int hi = e > N - 1 ? N - 1 : e;
    int cin = hi - lo + 1; if (cin < 0) cin = 0;
    int iin = (i >= s && i <= e) ? 1 : 0;
    int pc = cin - iin;
    int nc = N - cin + iin;
    bool valid = (i < M) && (pc > 0) && (nc > 0);
    float pr = 0.f;
    if (valid)
        pr = ps / (float)(pc < 1 ? 1 : pc) + LAM_NEG * ns / (float)(nc < 1 ? 1 : nc);
    g_per_row[i] = pr;
    g_valid[i]   = valid ? 1 : 0;
}

// ---------------------------------------------------------------------------
// Pass 4: final scalar reduction
// ---------------------------------------------------------------------------
__global__ void k_final(float* __restrict__ out, int N) {
    float s = 0.f; int c = 0;
    for (int i = threadIdx.x; i < N; i += blockDim.x) {
        s += g_per_row[i];
        c += g_valid[i];
    }
    #pragma unroll
    for (int off = 16; off; off >>= 1) {
        s += __shfl_down_sync(0xffffffffu, s, off);
        c += __shfl_down_sync(0xffffffffu, c, off);
    }
    __shared__ float sh[8];
    __shared__ int   shc[8];
    if ((threadIdx.x & 31) == 0) { sh[threadIdx.x >> 5] = s; shc[threadIdx.x >> 5] = c; }
    __syncthreads();
    if (threadIdx.x < 8) {
        s = sh[threadIdx.x]; c = shc[threadIdx.x];
        #pragma unroll
        for (int off = 4; off; off >>= 1) {
            s += __shfl_down_sync(0xffu, s, off);
            c += __shfl_down_sync(0xffu, c, off);
        }
        if (threadIdx.x == 0) out[0] = (c > 0) ? s / (float)c : 0.f;
    }
}

// ---------------------------------------------------------------------------
// Launch
// ---------------------------------------------------------------------------
extern "C" void kernel_launch(void* const* d_in, const int* in_sizes, int n_in,
                              void* d_out, int out_size) {
    const float* cb     = (const float*)d_in[0];
    const int*   starts = (const int*)d_in[1];
    const int*   ends   = (const int*)d_in[2];
    const int*   pmaxi  = (const int*)d_in[3];

    int N = in_sizes[1];                 // starts has N elements
    int d = in_sizes[0] / N;             // codebook is N x d

    int njt = (N + 127) / 128;
    int nit = (N + 127) / 128;

    k_norms<<<N, 256>>>(cb, N, d);

    dim3 grid(njt, nit);
    k_main<<<grid, 256>>>(cb, starts, ends, pmaxi, N, d);

    k_rowsum<<<(N + 255) / 256, 256>>>(starts, ends, pmaxi, N, njt);

    k_final<<<1, 256>>>((float*)d_out, N);
}